// round 9
// baseline (speedup 1.0000x reference)
#include <cuda_runtime.h>
#include <cstdint>

namespace {
constexpr int L2C   = 65536;
constexpr int NC    = 2 * L2C;      // 131072
constexpr int FINC  = 8;
constexpr int FOUTC = 8;
constexpr int KC    = 13;
constexpr int IK    = FINC * KC;    // 104
constexpr int EPB   = 32;           // edges per block
constexpr int TPB   = 256;
constexpr int CHE   = 4;            // edges per chunk
constexpr int NCH   = EPB / CHE;    // 8 chunks
constexpr int NST   = 3;            // ring stages
constexpr int WPE   = IK * FOUTC;   // 832 mask elements per edge
constexpr int CHWRD = CHE * WPE;    // 3328 elements per chunk
constexpr int CHB_W = CHWRD * 4;    // 13312 B per chunk (word masks)
}

// x transposed to (N, FIN): one gathered column = one 32B sector.
__device__ __align__(16) float g_xt[(size_t)NC * FINC];
// 0 => 4-byte mask words ({0,1} int32 or {0,1.0f} float32); 1 => 1-byte elements
__device__ int g_mask_is_byte;

__global__ __launch_bounds__(TPB) void prep_kernel(const float* __restrict__ x,
                                                   const uint32_t* __restrict__ M) {
    if (blockIdx.x == 0 && threadIdx.x < 32) {
        int bad = 0;
        for (int i = threadIdx.x; i < 1024; i += 32) {
            uint32_t w = M[i];
            if (!(w == 0u || w == 1u || w == 0x3f800000u)) bad = 1;
        }
        bad = __any_sync(0xffffffffu, bad);
        if (threadIdx.x == 0) g_mask_is_byte = bad;
    }
    int j = blockIdx.x * blockDim.x + threadIdx.x;
    if (j >= NC) return;
    float4 a, b;
    a.x = x[0 * NC + j]; a.y = x[1 * NC + j]; a.z = x[2 * NC + j]; a.w = x[3 * NC + j];
    b.x = x[4 * NC + j]; b.y = x[5 * NC + j]; b.z = x[6 * NC + j]; b.w = x[7 * NC + j];
    float4* dst = reinterpret_cast<float4*>(g_xt) + (size_t)j * 2;
    dst[0] = a;
    dst[1] = b;
}

// ---- mbarrier + 1D bulk-TMA helpers ----
__device__ __forceinline__ void mbar_init(uint32_t mbar, uint32_t count) {
    asm volatile("mbarrier.init.shared.b64 [%0], %1;" :: "r"(mbar), "r"(count) : "memory");
}
__device__ __forceinline__ void mbar_expect_tx(uint32_t mbar, uint32_t bytes) {
    asm volatile("mbarrier.arrive.expect_tx.shared.b64 _, [%0], %1;"
                 :: "r"(mbar), "r"(bytes) : "memory");
}
__device__ __forceinline__ void mbar_wait(uint32_t mbar, uint32_t parity) {
    asm volatile(
        "{\n\t"
        ".reg .pred P;\n\t"
        "WAIT_%=:\n\t"
        "mbarrier.try_wait.parity.acquire.cta.shared::cta.b64 P, [%0], %1, 0x989680;\n\t"
        "@P bra.uni DONE_%=;\n\t"
        "bra.uni WAIT_%=;\n\t"
        "DONE_%=:\n\t"
        "}"
        :: "r"(mbar), "r"(parity) : "memory");
}
__device__ __forceinline__ void tma_1d(uint32_t dst_smem, const void* src,
                                       uint32_t bytes, uint32_t mbar) {
    asm volatile(
        "cp.async.bulk.shared::cta.global.mbarrier::complete_tx::bytes [%0], [%1], %2, [%3];"
        :: "r"(dst_smem), "l"(src), "r"(bytes), "r"(mbar) : "memory");
}

__global__ __launch_bounds__(TPB, 4) void edge_kernel(
    const float* __restrict__ Wh, const float* __restrict__ Wv,
    const float* __restrict__ bh, const float* __restrict__ bv,
    const uint8_t* __restrict__ Mh, const uint8_t* __restrict__ Mv,
    const int* __restrict__ Kh, const int* __restrict__ Kv,
    const int* __restrict__ ELh, const int* __restrict__ ELv,
    float* __restrict__ out)
{
    const bool vert = (blockIdx.y != 0);
    const float*   W    = vert ? Wv  : Wh;
    const float*   bias = vert ? bv  : bh;
    const uint8_t* M    = vert ? Mv  : Mh;
    const int*     KER  = vert ? Kv  : Kh;
    const int*     EL   = vert ? ELv : ELh;

    __shared__ __align__(128) uint32_t mbuf[NST * CHWRD];  // 39936 B raw mask ring
    __shared__ __align__(8)   uint64_t mbar[NST];
    __shared__ int   kers[EPB * KC];
    __shared__ int   els[EPB];
    __shared__ float bsh[FOUTC];

    const int tid = threadIdx.x;
    const int e0  = blockIdx.x * EPB;

    // ---- small tables ----
    for (int t = tid; t < EPB * KC; t += TPB) kers[t] = KER[e0 * KC + t];
    if (tid < EPB)   els[tid] = EL[e0 + tid];
    if (tid < FOUTC) bsh[tid] = bias[tid];

    const uint32_t mbar_s = (uint32_t)__cvta_generic_to_shared(&mbar[0]);
    const uint32_t mb_s   = (uint32_t)__cvta_generic_to_shared(mbuf);

    if (tid == 0) {
        mbar_init(mbar_s + 0, 1);
        mbar_init(mbar_s + 8, 1);
        mbar_init(mbar_s + 16, 1);
        asm volatile("fence.proxy.async.shared::cta;" ::: "memory");
    }
    __syncthreads();   // mbarriers + kers visible

    // ---- roles: tid = cel<2b> | lp<6b>, lp = o*8 + ii ----
    const int cel = tid >> 6;
    const int lp  = tid & 63;
    const int o   = lp >> 3;
    const int ii  = lp & 7;

    // W row (o, ii): 13 registers (L2-resident)
    float wreg[KC];
    #pragma unroll
    for (int k = 0; k < KC; k++) wreg[k] = W[lp * KC + k];

    const int isbyte = g_mask_is_byte;
    const uint32_t chb = isbyte ? CHWRD : CHB_W;          // bytes per chunk
    const uint8_t* Mbase = M + (size_t)e0 * WPE * (isbyte ? 1 : 4);

    // ---- prologue: launch chunks 0 and 1 ----
    if (tid == 0) {
        mbar_expect_tx(mbar_s + 0, chb);
        tma_1d(mb_s + 0 * CHB_W, Mbase, chb, mbar_s + 0);
        mbar_expect_tx(mbar_s + 8, chb);
        tma_1d(mb_s + 1 * CHB_W, Mbase + (size_t)chb, chb, mbar_s + 8);
    }

    const float SCALE = (float)((2.0 + 2.0 * 2.718281828459045235) /
                                (2.718281828459045235 - 1.0));

    #pragma unroll 1
    for (int c = 0; c < NCH; c++) {
        const int s = c % NST;

        // ---- producer: launch chunk c+2 into stage (c+2)%3 ----
        if (tid == 0 && c + 2 < NCH) {
            const int n  = c + 2;
            const int sn = n % NST;
            mbar_expect_tx(mbar_s + sn * 8, chb);
            tma_1d(mb_s + sn * CHB_W, Mbase + (size_t)n * chb, chb, mbar_s + sn * 8);
        }

        // ---- gather x for chunk c into registers (independent of mask wait) ----
        const int eg = c * CHE + cel;
        float xv[KC];
        #pragma unroll
        for (int k = 0; k < KC; k++) {
            int j = kers[eg * KC + k];
            xv[k] = g_xt[(size_t)j * FINC + ii];
        }

        // ---- wait for chunk c ----
        mbar_wait(mbar_s + s * 8, (c / NST) & 1);

        // ---- compute: thread (cel, o, ii) does 13 MACs ----
        float acc = 0.0f;
        if (!isbyte) {
            const uint32_t* mrow = mbuf + s * CHWRD + cel * WPE + lp * KC;
            #pragma unroll
            for (int k = 0; k < KC; k++)
                if (mrow[k]) acc = fmaf(wreg[k], xv[k], acc);
        } else {
            const uint8_t* mrow = reinterpret_cast<const uint8_t*>(mbuf) +
                                  s * CHB_W + cel * WPE + lp * KC;
            #pragma unroll
            for (int k = 0; k < KC; k++)
                if (mrow[k]) acc = fmaf(wreg[k], xv[k], acc);
        }

        // reduce over input features (lane bits 0..2)
        acc += __shfl_xor_sync(0xffffffffu, acc, 1);
        acc += __shfl_xor_sync(0xffffffffu, acc, 2);
        acc += __shfl_xor_sync(0xffffffffu, acc, 4);

        if (ii == 0) {
            float z = acc + bsh[o];
            float sgm = 1.0f / (1.0f + __expf(-z));
            out[(size_t)o * NC + els[eg]] = (sgm - 0.5f) * SCALE;
        }
        __syncthreads();   // consumers done with stage s -> TMA for chunk c+3 may overwrite
    }
}

extern "C" void kernel_launch(void* const* d_in, const int* in_sizes, int n_in,
                              void* d_out, int out_size) {
    const float*   x   = (const float*)  d_in[0];
    const float*   Wh  = (const float*)  d_in[1];
    const float*   Wv  = (const float*)  d_in[2];
    const float*   bh  = (const float*)  d_in[3];
    const float*   bv  = (const float*)  d_in[4];
    const uint8_t* Mh  = (const uint8_t*)d_in[5];
    const uint8_t* Mv  = (const uint8_t*)d_in[6];
    const int*     Kh  = (const int*)    d_in[7];
    const int*     Kv  = (const int*)    d_in[8];
    const int*     ELh = (const int*)    d_in[9];
    const int*     ELv = (const int*)    d_in[10];
    float* out = (float*)d_out;

    prep_kernel<<<NC / TPB, TPB>>>(x, (const uint32_t*)Mh);

    dim3 grid(L2C / EPB, 2);   // y=0 horizontal branch, y=1 vertical
    edge_kernel<<<grid, TPB>>>(Wh, Wv, bh, bv, Mh, Mv, Kh, Kv, ELh, ELv, out);
}

// round 11
// speedup vs baseline: 1.2629x; 1.2629x over previous
#include <cuda_runtime.h>
#include <cstdint>

namespace {
constexpr int L2C   = 65536;
constexpr int NC    = 2 * L2C;      // 131072
constexpr int FINC  = 8;
constexpr int FOUTC = 8;
constexpr int KC    = 13;
constexpr int IK    = FINC * KC;    // 104
constexpr int EPB   = 32;           // edges per block
constexpr int TPB   = 256;
constexpr int CHE   = 4;            // edges per chunk
constexpr int NCH   = EPB / CHE;    // 8 chunks
constexpr int NST   = 3;            // ring stages
constexpr int WPE   = IK * FOUTC;   // 832 mask elements per edge
constexpr int CHWRD = CHE * WPE;    // 3328 elements per chunk
constexpr int CHB_W = CHWRD * 4;    // 13312 B per chunk (word masks)
constexpr int RING_B= NST * CHB_W;  // 39936 B dynamic smem ring
}

// x transposed to (N, FIN): one gathered column = one 32B sector.
__device__ __align__(16) float g_xt[(size_t)NC * FINC];
// 0 => 4-byte mask words ({0,1} int32 or {0,1.0f} float32); 1 => 1-byte elements
__device__ int g_mask_is_byte;

__global__ __launch_bounds__(TPB) void prep_kernel(const float* __restrict__ x,
                                                   const uint32_t* __restrict__ M) {
    if (blockIdx.x == 0 && threadIdx.x < 32) {
        int bad = 0;
        for (int i = threadIdx.x; i < 1024; i += 32) {
            uint32_t w = M[i];
            if (!(w == 0u || w == 1u || w == 0x3f800000u)) bad = 1;
        }
        bad = __any_sync(0xffffffffu, bad);
        if (threadIdx.x == 0) g_mask_is_byte = bad;
    }
    int j = blockIdx.x * blockDim.x + threadIdx.x;
    if (j >= NC) return;
    float4 a, b;
    a.x = x[0 * NC + j]; a.y = x[1 * NC + j]; a.z = x[2 * NC + j]; a.w = x[3 * NC + j];
    b.x = x[4 * NC + j]; b.y = x[5 * NC + j]; b.z = x[6 * NC + j]; b.w = x[7 * NC + j];
    float4* dst = reinterpret_cast<float4*>(g_xt) + (size_t)j * 2;
    dst[0] = a;
    dst[1] = b;
}

// ---- mbarrier + 1D bulk-TMA helpers ----
__device__ __forceinline__ void mbar_init(uint32_t mbar, uint32_t count) {
    asm volatile("mbarrier.init.shared.b64 [%0], %1;" :: "r"(mbar), "r"(count) : "memory");
}
__device__ __forceinline__ void mbar_expect_tx(uint32_t mbar, uint32_t bytes) {
    asm volatile("mbarrier.arrive.expect_tx.shared.b64 _, [%0], %1;"
                 :: "r"(mbar), "r"(bytes) : "memory");
}
__device__ __forceinline__ void mbar_wait(uint32_t mbar, uint32_t parity) {
    asm volatile(
        "{\n\t"
        ".reg .pred P;\n\t"
        "WAIT_%=:\n\t"
        "mbarrier.try_wait.parity.acquire.cta.shared::cta.b64 P, [%0], %1, 0x989680;\n\t"
        "@P bra.uni DONE_%=;\n\t"
        "bra.uni WAIT_%=;\n\t"
        "DONE_%=:\n\t"
        "}"
        :: "r"(mbar), "r"(parity) : "memory");
}
__device__ __forceinline__ void tma_1d(uint32_t dst_smem, const void* src,
                                       uint32_t bytes, uint32_t mbar) {
    asm volatile(
        "cp.async.bulk.shared::cta.global.mbarrier::complete_tx::bytes [%0], [%1], %2, [%3];"
        :: "r"(dst_smem), "l"(src), "r"(bytes), "r"(mbar) : "memory");
}

__global__ __launch_bounds__(TPB, 4) void edge_kernel(
    const float* __restrict__ Wh, const float* __restrict__ Wv,
    const float* __restrict__ bh, const float* __restrict__ bv,
    const uint8_t* __restrict__ Mh, const uint8_t* __restrict__ Mv,
    const int* __restrict__ Kh, const int* __restrict__ Kv,
    const int* __restrict__ ELh, const int* __restrict__ ELv,
    float* __restrict__ out)
{
    extern __shared__ __align__(128) uint32_t mbuf[];   // NST * CHWRD words (ring)

    const bool vert = (blockIdx.y != 0);
    const float*   W    = vert ? Wv  : Wh;
    const float*   bias = vert ? bv  : bh;
    const uint8_t* M    = vert ? Mv  : Mh;
    const int*     KER  = vert ? Kv  : Kh;
    const int*     EL   = vert ? ELv : ELh;

    __shared__ __align__(16) float    xsf[EPB * IK];     // 13312 B
    __shared__ __align__(8)  uint64_t mbar[NST];
    __shared__ int   kers[EPB * KC];
    __shared__ int   els[EPB];
    __shared__ float bsh[FOUTC];

    const int tid = threadIdx.x;
    const int e0  = blockIdx.x * EPB;

    // ---- small tables ----
    for (int t = tid; t < EPB * KC; t += TPB) kers[t] = KER[e0 * KC + t];
    if (tid < EPB)   els[tid] = EL[e0 + tid];
    if (tid < FOUTC) bsh[tid] = bias[tid];

    const uint32_t mbar_s = (uint32_t)__cvta_generic_to_shared(&mbar[0]);
    const uint32_t mb_s   = (uint32_t)__cvta_generic_to_shared(mbuf);

    if (tid == 0) {
        mbar_init(mbar_s + 0, 1);
        mbar_init(mbar_s + 8, 1);
        mbar_init(mbar_s + 16, 1);
        asm volatile("fence.proxy.async.shared::cta;" ::: "memory");
    }
    __syncthreads();   // mbarriers + kers visible

    // ---- roles: tid = cel<2b> | lp<6b>, lp = o*8 + ii ----
    const int cel = tid >> 6;
    const int lp  = tid & 63;
    const int o   = lp >> 3;
    const int ii  = lp & 7;

    // W row (o, ii): 13 registers (L2-resident)
    float wreg[KC];
    #pragma unroll
    for (int k = 0; k < KC; k++) wreg[k] = W[lp * KC + k];

    const int isbyte = g_mask_is_byte;
    const uint32_t chb = isbyte ? CHWRD : CHB_W;          // bytes per chunk
    const uint8_t* Mbase = M + (size_t)e0 * WPE * (isbyte ? 1 : 4);

    // ---- prologue: chunks 0 and 1 in flight before anything else ----
    if (tid == 0) {
        mbar_expect_tx(mbar_s + 0, chb);
        tma_1d(mb_s + 0 * CHB_W, Mbase, chb, mbar_s + 0);
        mbar_expect_tx(mbar_s + 8, chb);
        tma_1d(mb_s + 1 * CHB_W, Mbase + (size_t)chb, chb, mbar_s + 8);
    }

    // ---- x gather once per block (overlaps chunk-0/1 TMA) ----
    {
        const int gel = tid >> 3, gi = tid & 7;
        #pragma unroll
        for (int k = 0; k < KC; k++) {
            int j = kers[gel * KC + k];
            xsf[gel * IK + gi * KC + k] = g_xt[(size_t)j * FINC + gi];
        }
    }
    __syncthreads();   // xsf published

    const float SCALE = (float)((2.0 + 2.0 * 2.718281828459045235) /
                                (2.718281828459045235 - 1.0));

    #pragma unroll 1
    for (int c = 0; c < NCH; c++) {
        const int s = c % NST;

        // ---- producer: chunk c+2 into stage (c+2)%3 (that stage's consumers
        //      finished chunk c-1 last iteration; barrier below ordered it) ----
        if (tid == 0 && c + 2 < NCH) {
            const int n  = c + 2;
            const int sn = n % NST;
            mbar_expect_tx(mbar_s + sn * 8, chb);
            tma_1d(mb_s + sn * CHB_W, Mbase + (size_t)n * chb, chb, mbar_s + sn * 8);
        }

        // ---- wait for chunk c (issued 2 iterations ago -> fast path) ----
        mbar_wait(mbar_s + s * 8, (c / NST) & 1);

        // ---- compute chunk c: thread (cel, o, ii) does 13 MACs ----
        const int eg = c * CHE + cel;
        const float* xrow = &xsf[eg * IK + ii * KC];

        float acc = 0.0f;
        if (!isbyte) {
            const uint32_t* mrow = mbuf + s * CHWRD + cel * WPE + lp * KC;
            #pragma unroll
            for (int k = 0; k < KC; k++)
                if (mrow[k]) acc = fmaf(wreg[k], xrow[k], acc);
        } else {
            const uint8_t* mrow = reinterpret_cast<const uint8_t*>(mbuf) +
                                  s * CHB_W + cel * WPE + lp * KC;
            #pragma unroll
            for (int k = 0; k < KC; k++)
                if (mrow[k]) acc = fmaf(wreg[k], xrow[k], acc);
        }

        // reduce over input features (lane bits 0..2)
        acc += __shfl_xor_sync(0xffffffffu, acc, 1);
        acc += __shfl_xor_sync(0xffffffffu, acc, 2);
        acc += __shfl_xor_sync(0xffffffffu, acc, 4);

        if (ii == 0) {
            float z = acc + bsh[o];
            float sgm = 1.0f / (1.0f + __expf(-z));
            out[(size_t)o * NC + els[eg]] = (sgm - 0.5f) * SCALE;
        }
        __syncthreads();   // all consumers done with stage s -> safe for chunk c+3
    }
}

extern "C" void kernel_launch(void* const* d_in, const int* in_sizes, int n_in,
                              void* d_out, int out_size) {
    const float*   x   = (const float*)  d_in[0];
    const float*   Wh  = (const float*)  d_in[1];
    const float*   Wv  = (const float*)  d_in[2];
    const float*   bh  = (const float*)  d_in[3];
    const float*   bv  = (const float*)  d_in[4];
    const uint8_t* Mh  = (const uint8_t*)d_in[5];
    const uint8_t* Mv  = (const uint8_t*)d_in[6];
    const int*     Kh  = (const int*)    d_in[7];
    const int*     Kv  = (const int*)    d_in[8];
    const int*     ELh = (const int*)    d_in[9];
    const int*     ELv = (const int*)    d_in[10];
    float* out = (float*)d_out;

    cudaFuncSetAttribute(edge_kernel,
                         cudaFuncAttributeMaxDynamicSharedMemorySize, RING_B);

    prep_kernel<<<NC / TPB, TPB>>>(x, (const uint32_t*)Mh);

    dim3 grid(L2C / EPB, 2);   // y=0 horizontal branch, y=1 vertical
    edge_kernel<<<grid, TPB, RING_B>>>(Wh, Wv, bh, bv, Mh, Mv, Kh, Kv, ELh, ELv, out);
}

// round 12
// speedup vs baseline: 1.2671x; 1.0033x over previous
#include <cuda_runtime.h>
#include <cstdint>

namespace {
constexpr int L2C   = 65536;
constexpr int NC    = 2 * L2C;      // 131072
constexpr int FINC  = 8;
constexpr int FOUTC = 8;
constexpr int KC    = 13;
constexpr int IK    = FINC * KC;    // 104
constexpr int EPB   = 32;           // edges per block
constexpr int TPB   = 256;          // 8 warps
constexpr int NWARP = 8;
constexpr int TASKS = 8;            // tasks per warp
constexpr int NST   = 3;            // private ring stages per warp
constexpr int WPE   = IK * FOUTC;   // 832 mask elements per edge
constexpr int HWRD  = WPE / 2;      // 416 words per (edge, o-half) task
constexpr int STB_W = HWRD * 4;     // 1664 B per stage (word masks)
constexpr int WRING = NST * STB_W;  // 4992 B per-warp ring
constexpr int RING_B= NWARP * WRING;// 39936 B dynamic smem
}

// x transposed to (N, FIN): one gathered column = one 32B sector.
__device__ __align__(16) float g_xt[(size_t)NC * FINC];
// 0 => 4-byte mask words ({0,1} int32 or {0,1.0f} float32); 1 => 1-byte elements
__device__ int g_mask_is_byte;

__global__ __launch_bounds__(TPB) void prep_kernel(const float* __restrict__ x,
                                                   const uint32_t* __restrict__ M) {
    if (blockIdx.x == 0 && threadIdx.x < 32) {
        int bad = 0;
        for (int i = threadIdx.x; i < 1024; i += 32) {
            uint32_t w = M[i];
            if (!(w == 0u || w == 1u || w == 0x3f800000u)) bad = 1;
        }
        bad = __any_sync(0xffffffffu, bad);
        if (threadIdx.x == 0) g_mask_is_byte = bad;
    }
    int j = blockIdx.x * blockDim.x + threadIdx.x;
    if (j >= NC) return;
    float4 a, b;
    a.x = x[0 * NC + j]; a.y = x[1 * NC + j]; a.z = x[2 * NC + j]; a.w = x[3 * NC + j];
    b.x = x[4 * NC + j]; b.y = x[5 * NC + j]; b.z = x[6 * NC + j]; b.w = x[7 * NC + j];
    float4* dst = reinterpret_cast<float4*>(g_xt) + (size_t)j * 2;
    dst[0] = a;
    dst[1] = b;
}

// ---- mbarrier + 1D bulk-TMA helpers ----
__device__ __forceinline__ void mbar_init(uint32_t mbar, uint32_t count) {
    asm volatile("mbarrier.init.shared.b64 [%0], %1;" :: "r"(mbar), "r"(count) : "memory");
}
__device__ __forceinline__ void mbar_expect_tx(uint32_t mbar, uint32_t bytes) {
    asm volatile("mbarrier.arrive.expect_tx.shared.b64 _, [%0], %1;"
                 :: "r"(mbar), "r"(bytes) : "memory");
}
__device__ __forceinline__ void mbar_wait(uint32_t mbar, uint32_t parity) {
    asm volatile(
        "{\n\t"
        ".reg .pred P;\n\t"
        "WAIT_%=:\n\t"
        "mbarrier.try_wait.parity.acquire.cta.shared::cta.b64 P, [%0], %1, 0x989680;\n\t"
        "@P bra.uni DONE_%=;\n\t"
        "bra.uni WAIT_%=;\n\t"
        "DONE_%=:\n\t"
        "}"
        :: "r"(mbar), "r"(parity) : "memory");
}
__device__ __forceinline__ void tma_1d(uint32_t dst_smem, const void* src,
                                       uint32_t bytes, uint32_t mbar) {
    asm volatile(
        "cp.async.bulk.shared::cta.global.mbarrier::complete_tx::bytes [%0], [%1], %2, [%3];"
        :: "r"(dst_smem), "l"(src), "r"(bytes), "r"(mbar) : "memory");
}

__global__ __launch_bounds__(TPB, 4) void edge_kernel(
    const float* __restrict__ Wh, const float* __restrict__ Wv,
    const float* __restrict__ bh, const float* __restrict__ bv,
    const uint8_t* __restrict__ Mh, const uint8_t* __restrict__ Mv,
    const int* __restrict__ Kh, const int* __restrict__ Kv,
    const int* __restrict__ ELh, const int* __restrict__ ELv,
    float* __restrict__ out)
{
    extern __shared__ __align__(128) uint32_t mbuf[];   // per-warp rings

    const bool vert = (blockIdx.y != 0);
    const float*   W    = vert ? Wv  : Wh;
    const float*   bias = vert ? bv  : bh;
    const uint8_t* M    = vert ? Mv  : Mh;
    const int*     KER  = vert ? Kv  : Kh;
    const int*     EL   = vert ? ELv : ELh;

    __shared__ __align__(16) float    xsf[EPB * IK];        // 13312 B
    __shared__ __align__(8)  uint64_t mbar[NWARP * NST];
    __shared__ int   kers[EPB * KC];
    __shared__ int   els[EPB];
    __shared__ float bsh[FOUTC];

    const int tid  = threadIdx.x;
    const int lane = tid & 31;
    const int w    = tid >> 5;          // warp 0..7
    const int e0   = blockIdx.x * EPB;

    // ---- small tables ----
    for (int t = tid; t < EPB * KC; t += TPB) kers[t] = KER[e0 * KC + t];
    if (tid < EPB)   els[tid] = EL[e0 + tid];
    if (tid < FOUTC) bsh[tid] = bias[tid];

    const uint32_t mbar_base = (uint32_t)__cvta_generic_to_shared(&mbar[0]) + w * NST * 8;
    const uint32_t ring_base = (uint32_t)__cvta_generic_to_shared(mbuf) + w * WRING;

    if (lane == 0) {
        mbar_init(mbar_base + 0, 1);
        mbar_init(mbar_base + 8, 1);
        mbar_init(mbar_base + 16, 1);
        asm volatile("fence.proxy.async.shared::cta;" ::: "memory");
    }
    __syncthreads();   // kers + all mbarriers visible

    // ---- warp roles: h = o-half, eo = edge slot; lane = o_local*8 + ii ----
    const int h  = w >> 2;
    const int eo = w & 3;
    const int ii = lane & 7;
    const int ol = lane >> 3;
    const int o  = h * 4 + ol;

    // W row for (o, ii): 13 registers (L2-resident)
    float wreg[KC];
    #pragma unroll
    for (int k = 0; k < KC; k++) wreg[k] = W[(h * 32 + lane) * KC + k];

    const int isbyte = g_mask_is_byte;
    const uint32_t txb  = isbyte ? HWRD : STB_W;          // bytes per task transfer
    const uint8_t* Mb   = M + ((size_t)e0 * WPE + h * HWRD) * (isbyte ? 1 : 4);
    const size_t   estr = (size_t)WPE * (isbyte ? 1 : 4); // bytes per edge

    // ---- prologue: tasks 0,1 in flight ----
    if (lane == 0) {
        mbar_expect_tx(mbar_base + 0, txb);
        tma_1d(ring_base + 0 * STB_W, Mb + (size_t)(eo) * estr, txb, mbar_base + 0);
        mbar_expect_tx(mbar_base + 8, txb);
        tma_1d(ring_base + 1 * STB_W, Mb + (size_t)(eo + 4) * estr, txb, mbar_base + 8);
    }

    // ---- x gather once per block (overlaps TMA) ----
    {
        const int gel = tid >> 3, gi = tid & 7;
        #pragma unroll
        for (int k = 0; k < KC; k++) {
            int j = kers[gel * KC + k];
            xsf[gel * IK + gi * KC + k] = g_xt[(size_t)j * FINC + gi];
        }
    }
    __syncthreads();   // xsf published (only block-wide sync before loop)

    const float SCALE = (float)((2.0 + 2.0 * 2.718281828459045235) /
                                (2.718281828459045235 - 1.0));

    const uint32_t* ring_w = mbuf + w * (WRING / 4);

    #pragma unroll 1
    for (int t = 0; t < TASKS; t++) {
        const int s = t % NST;

        // ---- issue task t+2 into stage (t+2)%3 ----
        if (lane == 0 && t + 2 < TASKS) {
            const int sn = (t + 2) % NST;
            mbar_expect_tx(mbar_base + sn * 8, txb);
            tma_1d(ring_base + sn * STB_W, Mb + (size_t)(eo + 4 * (t + 2)) * estr,
                   txb, mbar_base + sn * 8);
        }

        // ---- wait for task t (issued 2 tasks ago -> fast path) ----
        mbar_wait(mbar_base + s * 8, (t / 3) & 1);

        // ---- compute: lane (ol, ii) does 13 MACs for edge e ----
        const int e = eo + 4 * t;                 // block-local edge
        const float* xrow = &xsf[e * IK + ii * KC];

        float acc = 0.0f;
        if (!isbyte) {
            const uint32_t* mrow = ring_w + s * HWRD + lane * KC;
            #pragma unroll
            for (int k = 0; k < KC; k++)
                if (mrow[k]) acc = fmaf(wreg[k], xrow[k], acc);
        } else {
            const uint8_t* mrow = reinterpret_cast<const uint8_t*>(ring_w) +
                                  s * HWRD + lane * KC;
            #pragma unroll
            for (int k = 0; k < KC; k++)
                if (mrow[k]) acc = fmaf(wreg[k], xrow[k], acc);
        }

        // reduce over input features (lane bits 0..2, stays in-warp)
        acc += __shfl_xor_sync(0xffffffffu, acc, 1);
        acc += __shfl_xor_sync(0xffffffffu, acc, 2);
        acc += __shfl_xor_sync(0xffffffffu, acc, 4);

        if (ii == 0) {
            float z = acc + bsh[o];
            float sgm = 1.0f / (1.0f + __expf(-z));
            out[(size_t)o * NC + els[e]] = (sgm - 0.5f) * SCALE;
        }
        __syncwarp();   // all lanes done with stage s -> reusable at t+3
    }
}

extern "C" void kernel_launch(void* const* d_in, const int* in_sizes, int n_in,
                              void* d_out, int out_size) {
    const float*   x   = (const float*)  d_in[0];
    const float*   Wh  = (const float*)  d_in[1];
    const float*   Wv  = (const float*)  d_in[2];
    const float*   bh  = (const float*)  d_in[3];
    const float*   bv  = (const float*)  d_in[4];
    const uint8_t* Mh  = (const uint8_t*)d_in[5];
    const uint8_t* Mv  = (const uint8_t*)d_in[6];
    const int*     Kh  = (const int*)    d_in[7];
    const int*     Kv  = (const int*)    d_in[8];
    const int*     ELh = (const int*)    d_in[9];
    const int*     ELv = (const int*)    d_in[10];
    float* out = (float*)d_out;

    cudaFuncSetAttribute(edge_kernel,
                         cudaFuncAttributeMaxDynamicSharedMemorySize, RING_B);

    prep_kernel<<<NC / TPB, TPB>>>(x, (const uint32_t*)Mh);

    dim3 grid(L2C / EPB, 2);   // y=0 horizontal branch, y=1 vertical
    edge_kernel<<<grid, TPB, RING_B>>>(Wh, Wv, bh, bv, Mh, Mv, Kh, Kv, ELh, ELv, out);
}

// round 13
// speedup vs baseline: 1.2983x; 1.0246x over previous
#include <cuda_runtime.h>
#include <cstdint>

namespace {
constexpr int L2C   = 65536;
constexpr int NC    = 2 * L2C;      // 131072
constexpr int FINC  = 8;
constexpr int FOUTC = 8;
constexpr int KC    = 13;
constexpr int IK    = FINC * KC;    // 104
constexpr int EPB   = 32;           // edges per block
constexpr int TPB   = 256;
constexpr int CHE   = 4;            // edges per chunk
constexpr int NCH   = EPB / CHE;    // 8 chunks
constexpr int WPE   = IK * FOUTC;   // 832 mask elements per edge
constexpr int CHWRD = CHE * WPE;    // 3328 elements per chunk
constexpr int CHB_W = CHWRD * 4;    // 13312 B per chunk (word masks)
}

// x transposed to (N, FIN): one gathered column = one 32B sector.
__device__ __align__(16) float g_xt[(size_t)NC * FINC];
// 0 => 4-byte mask words ({0,1} int32 or {0,1.0f} float32); 1 => 1-byte elements
__device__ int g_mask_is_byte;

__global__ __launch_bounds__(TPB) void prep_kernel(const float* __restrict__ x,
                                                   const uint32_t* __restrict__ M) {
    if (blockIdx.x == 0 && threadIdx.x < 32) {
        int bad = 0;
        #pragma unroll
        for (int r = 0; r < 8; r++) {               // 256 words, 8 independent loads/lane
            uint32_t w = M[r * 32 + threadIdx.x];
            if (!(w == 0u || w == 1u || w == 0x3f800000u)) bad = 1;
        }
        bad = __any_sync(0xffffffffu, bad);
        if (threadIdx.x == 0) g_mask_is_byte = bad;
    }
    int j = blockIdx.x * blockDim.x + threadIdx.x;
    if (j >= NC) return;
    float4 a, b;
    a.x = x[0 * NC + j]; a.y = x[1 * NC + j]; a.z = x[2 * NC + j]; a.w = x[3 * NC + j];
    b.x = x[4 * NC + j]; b.y = x[5 * NC + j]; b.z = x[6 * NC + j]; b.w = x[7 * NC + j];
    float4* dst = reinterpret_cast<float4*>(g_xt) + (size_t)j * 2;
    dst[0] = a;
    dst[1] = b;
}

__device__ __forceinline__ void cp16(uint32_t dst_smem, const void* src) {
    asm volatile("cp.async.cg.shared.global [%0], [%1], 16;"
                 :: "r"(dst_smem), "l"(src) : "memory");
}
__device__ __forceinline__ void cp_commit() {
    asm volatile("cp.async.commit_group;" ::: "memory");
}
template <int N> __device__ __forceinline__ void cp_wait() {
    asm volatile("cp.async.wait_group %0;" :: "n"(N) : "memory");
}

__global__ __launch_bounds__(TPB, 5) void edge_kernel(
    const float* __restrict__ Wh, const float* __restrict__ Wv,
    const float* __restrict__ bh, const float* __restrict__ bv,
    const uint8_t* __restrict__ Mh, const uint8_t* __restrict__ Mv,
    const int* __restrict__ Kh, const int* __restrict__ Kv,
    const int* __restrict__ ELh, const int* __restrict__ ELv,
    float* __restrict__ out)
{
    const bool vert = (blockIdx.y != 0);
    const float*   W    = vert ? Wv  : Wh;
    const float*   bias = vert ? bv  : bh;
    const uint8_t* M    = vert ? Mv  : Mh;
    const int*     KER  = vert ? Kv  : Kh;
    const int*     EL   = vert ? ELv : ELh;

    __shared__ __align__(16) uint32_t mbuf[2 * CHWRD];     // 26624 B mask ring
    __shared__ __align__(16) float    xsf[EPB * IK];       // 13312 B
    __shared__ int   kers[EPB * KC];
    __shared__ int   els[EPB];
    __shared__ float bsh[FOUTC];

    const int tid = threadIdx.x;
    const int e0  = blockIdx.x * EPB;

    // ---- small tables ----
    for (int t = tid; t < EPB * KC; t += TPB) kers[t] = KER[e0 * KC + t];
    if (tid < EPB)   els[tid] = EL[e0 + tid];
    if (tid < FOUTC) bsh[tid] = bias[tid];

    // ---- roles: tid = cel<2b> | lp<6b>,  lp = o*8 + i ----
    const int cel = tid >> 6;            // chunk-local edge 0..3
    const int lp  = tid & 63;
    const int o   = lp >> 3;
    const int ii  = lp & 7;

    // W row (o, ii): 13 registers (L2-resident)
    float wreg[KC];
    #pragma unroll
    for (int k = 0; k < KC; k++) wreg[k] = __ldg(&W[lp * KC + k]);

    const int isbyte = g_mask_is_byte;
    const int esz    = isbyte ? 1 : 4;
    const int chb    = CHWRD * esz;                 // bytes per chunk
    const int nops   = chb >> 4;                    // 16B cp.async ops per chunk
    const uint8_t* Mbase = M + (size_t)e0 * WPE * esz;
    const uint32_t mb_s  = (uint32_t)__cvta_generic_to_shared(mbuf);

    // ---- prologue: chunks 0 AND 1 in flight before the x gather ----
    for (int u = tid; u < nops; u += TPB)
        cp16(mb_s + u * 16, Mbase + (size_t)u * 16);
    cp_commit();                                    // group: chunk 0
    for (int u = tid; u < nops; u += TPB)
        cp16(mb_s + CHB_W + u * 16, Mbase + (size_t)chb + (size_t)u * 16);
    cp_commit();                                    // group: chunk 1

    __syncthreads();   // kers visible for gather

    // ---- gather x once per block: thread (gel, gi) supplies feature gi of edge gel ----
    {
        const int gel = tid >> 3, gi = tid & 7;
        #pragma unroll
        for (int k = 0; k < KC; k++) {
            int j = kers[gel * KC + k];
            xsf[gel * IK + gi * KC + k] = g_xt[(size_t)j * FINC + gi];
        }
    }

    const float SCALE = (float)((2.0 + 2.0 * 2.718281828459045235) /
                                (2.718281828459045235 - 1.0));

    #pragma unroll 1
    for (int c = 0; c < NCH; c++) {
        const int bsel = c & 1;

        // ---- issue chunk c+1 into the other buffer (chunks 0,1 pre-issued) ----
        if (c >= 1 && c + 1 < NCH) {
            const uint8_t* src = Mbase + (size_t)(c + 1) * chb;
            const uint32_t dst = mb_s + (bsel ^ 1) * CHB_W;
            for (int u = tid; u < nops; u += TPB)
                cp16(dst + u * 16, src + (size_t)u * 16);
            cp_commit();
        }
        // outstanding groups now: {c, c+1} (or just {c} on last iter)
        if (c + 1 < NCH) cp_wait<1>();   // chunk c landed
        else             cp_wait<0>();
        __syncthreads();                 // publish chunk c; xsf ready (c==0)

        // ---- compute chunk c: thread (cel, o, ii) does 13 MACs ----
        const int eg = c * CHE + cel;
        const float* xrow = &xsf[eg * IK + ii * KC];

        float acc = 0.0f;
        if (!isbyte) {
            const uint32_t* mrow = mbuf + bsel * CHWRD + cel * WPE + lp * KC;
            #pragma unroll
            for (int k = 0; k < KC; k++)
                if (mrow[k]) acc = fmaf(wreg[k], xrow[k], acc);
        } else {
            const uint8_t* mrow = reinterpret_cast<const uint8_t*>(mbuf) +
                                  bsel * CHB_W + cel * WPE + lp * KC;
            #pragma unroll
            for (int k = 0; k < KC; k++)
                if (mrow[k]) acc = fmaf(wreg[k], xrow[k], acc);
        }

        // reduce over input features (lane bits 0..2)
        acc += __shfl_xor_sync(0xffffffffu, acc, 1);
        acc += __shfl_xor_sync(0xffffffffu, acc, 2);
        acc += __shfl_xor_sync(0xffffffffu, acc, 4);

        if (ii == 0) {
            float z = acc + bsh[o];
            float s = 1.0f / (1.0f + __expf(-z));
            out[(size_t)o * NC + els[eg]] = (s - 0.5f) * SCALE;
        }
        __syncthreads();   // buffer bsel free for reuse next iteration
    }
}

extern "C" void kernel_launch(void* const* d_in, const int* in_sizes, int n_in,
                              void* d_out, int out_size) {
    const float*   x   = (const float*)  d_in[0];
    const float*   Wh  = (const float*)  d_in[1];
    const float*   Wv  = (const float*)  d_in[2];
    const float*   bh  = (const float*)  d_in[3];
    const float*   bv  = (const float*)  d_in[4];
    const uint8_t* Mh  = (const uint8_t*)d_in[5];
    const uint8_t* Mv  = (const uint8_t*)d_in[6];
    const int*     Kh  = (const int*)    d_in[7];
    const int*     Kv  = (const int*)    d_in[8];
    const int*     ELh = (const int*)    d_in[9];
    const int*     ELv = (const int*)    d_in[10];
    float* out = (float*)d_out;

    prep_kernel<<<NC / TPB, TPB>>>(x, (const uint32_t*)Mh);

    dim3 grid(L2C / EPB, 2);   // y=0 horizontal branch, y=1 vertical
    edge_kernel<<<grid, TPB>>>(Wh, Wv, bh, bv, Mh, Mv, Kh, Kv, ELh, ELv, out);
}

// round 14
// speedup vs baseline: 1.4053x; 1.0825x over previous
#include <cuda_runtime.h>
#include <cstdint>

namespace {
constexpr int L2C   = 65536;
constexpr int NC    = 2 * L2C;      // 131072
constexpr int FINC  = 8;
constexpr int FOUTC = 8;
constexpr int KC    = 13;
constexpr int IK    = FINC * KC;    // 104
constexpr int EPB   = 32;           // edges per block
constexpr int TPB   = 256;
constexpr int CHE   = 4;            // edges per chunk
constexpr int NCH   = EPB / CHE;    // 8 chunks
constexpr int WPE   = IK * FOUTC;   // 832 mask elements per edge
constexpr int CHWRD = CHE * WPE;    // 3328 elements per chunk
constexpr int CHB_W = CHWRD * 4;    // 13312 B per chunk (word masks)
}

// x transposed to (N, FIN): one gathered column = one 32B sector.
__device__ __align__(16) float g_xt[(size_t)NC * FINC];
// 0 => 4-byte mask words ({0,1} int32 or {0,1.0f} float32); 1 => 1-byte elements
__device__ int g_mask_is_byte;

__global__ __launch_bounds__(TPB) void prep_kernel(const float* __restrict__ x,
                                                   const uint32_t* __restrict__ M) {
    if (blockIdx.x == 0 && threadIdx.x < 32) {
        int bad = 0;
        #pragma unroll
        for (int r = 0; r < 8; r++) {
            uint32_t w = M[r * 32 + threadIdx.x];
            if (!(w == 0u || w == 1u || w == 0x3f800000u)) bad = 1;
        }
        bad = __any_sync(0xffffffffu, bad);
        if (threadIdx.x == 0) g_mask_is_byte = bad;
    }
    int j = blockIdx.x * blockDim.x + threadIdx.x;
    if (j >= NC) return;
    float4 a, b;
    a.x = x[0 * NC + j]; a.y = x[1 * NC + j]; a.z = x[2 * NC + j]; a.w = x[3 * NC + j];
    b.x = x[4 * NC + j]; b.y = x[5 * NC + j]; b.z = x[6 * NC + j]; b.w = x[7 * NC + j];
    float4* dst = reinterpret_cast<float4*>(g_xt) + (size_t)j * 2;
    dst[0] = a;
    dst[1] = b;
}

// ---- cache-policy helpers ----
__device__ __forceinline__ uint64_t pol_evict_first() {
    uint64_t p;
    asm("createpolicy.fractional.L2::evict_first.b64 %0, 1.0;" : "=l"(p));
    return p;
}
__device__ __forceinline__ uint64_t pol_evict_last() {
    uint64_t p;
    asm("createpolicy.fractional.L2::evict_last.b64 %0, 1.0;" : "=l"(p));
    return p;
}
__device__ __forceinline__ void cp16_stream(uint32_t dst_smem, const void* src, uint64_t pol) {
    asm volatile("cp.async.cg.shared.global.L2::cache_hint [%0], [%1], 16, %2;"
                 :: "r"(dst_smem), "l"(src), "l"(pol) : "memory");
}
__device__ __forceinline__ void cp_commit() {
    asm volatile("cp.async.commit_group;" ::: "memory");
}
template <int N> __device__ __forceinline__ void cp_wait() {
    asm volatile("cp.async.wait_group %0;" :: "n"(N) : "memory");
}
__device__ __forceinline__ float ld_pin(const float* p, uint64_t pol) {
    float v;
    asm volatile("ld.global.nc.L2::cache_hint.f32 %0, [%1], %2;"
                 : "=f"(v) : "l"(p), "l"(pol));
    return v;
}

__global__ __launch_bounds__(TPB, 5) void edge_kernel(
    const float* __restrict__ Wh, const float* __restrict__ Wv,
    const float* __restrict__ bh, const float* __restrict__ bv,
    const uint8_t* __restrict__ Mh, const uint8_t* __restrict__ Mv,
    const int* __restrict__ Kh, const int* __restrict__ Kv,
    const int* __restrict__ ELh, const int* __restrict__ ELv,
    float* __restrict__ out)
{
    const bool vert = (blockIdx.y != 0);
    const float*   W    = vert ? Wv  : Wh;
    const float*   bias = vert ? bv  : bh;
    const uint8_t* M    = vert ? Mv  : Mh;
    const int*     KER  = vert ? Kv  : Kh;
    const int*     EL   = vert ? ELv : ELh;

    __shared__ __align__(16) uint32_t mbuf[2 * CHWRD];     // 26624 B mask ring
    __shared__ __align__(16) float    xsf[EPB * IK];       // 13312 B
    __shared__ int   kers[EPB * KC];
    __shared__ int   els[EPB];
    __shared__ float bsh[FOUTC];

    const int tid = threadIdx.x;
    const int e0  = blockIdx.x * EPB;

    const uint64_t polF = pol_evict_first();   // mask stream: don't occupy L2
    const uint64_t polL = pol_evict_last();    // g_xt: pin in L2

    // ---- small tables ----
    for (int t = tid; t < EPB * KC; t += TPB) kers[t] = KER[e0 * KC + t];
    if (tid < EPB)   els[tid] = EL[e0 + tid];
    if (tid < FOUTC) bsh[tid] = bias[tid];

    // ---- roles: tid = cel<2b> | lp<6b>,  lp = o*8 + i ----
    const int cel = tid >> 6;
    const int lp  = tid & 63;
    const int o   = lp >> 3;
    const int ii  = lp & 7;

    // W row (o, ii): 13 registers (L2-resident)
    float wreg[KC];
    #pragma unroll
    for (int k = 0; k < KC; k++) wreg[k] = __ldg(&W[lp * KC + k]);

    const int isbyte = g_mask_is_byte;
    const int esz    = isbyte ? 1 : 4;
    const int chb    = CHWRD * esz;                 // bytes per chunk
    const int nops   = chb >> 4;                    // 16B cp.async ops per chunk
    const uint8_t* Mbase = M + (size_t)e0 * WPE * esz;
    const uint32_t mb_s  = (uint32_t)__cvta_generic_to_shared(mbuf);

    // ---- prologue: chunks 0 AND 1 in flight before the x gather ----
    for (int u = tid; u < nops; u += TPB)
        cp16_stream(mb_s + u * 16, Mbase + (size_t)u * 16, polF);
    cp_commit();                                    // group: chunk 0
    for (int u = tid; u < nops; u += TPB)
        cp16_stream(mb_s + CHB_W + u * 16, Mbase + (size_t)chb + (size_t)u * 16, polF);
    cp_commit();                                    // group: chunk 1

    __syncthreads();   // kers visible for gather

    // ---- gather x once per block (L2-pinned loads) ----
    {
        const int gel = tid >> 3, gi = tid & 7;
        #pragma unroll
        for (int k = 0; k < KC; k++) {
            int j = kers[gel * KC + k];
            xsf[gel * IK + gi * KC + k] = ld_pin(&g_xt[(size_t)j * FINC + gi], polL);
        }
    }

    const float SCALE = (float)((2.0 + 2.0 * 2.718281828459045235) /
                                (2.718281828459045235 - 1.0));

    #pragma unroll 1
    for (int c = 0; c < NCH; c++) {
        const int bsel = c & 1;

        // ---- issue chunk c+1 into the other buffer (chunks 0,1 pre-issued) ----
        if (c >= 1 && c + 1 < NCH) {
            const uint8_t* src = Mbase + (size_t)(c + 1) * chb;
            const uint32_t dst = mb_s + (bsel ^ 1) * CHB_W;
            for (int u = tid; u < nops; u += TPB)
                cp16_stream(dst + u * 16, src + (size_t)u * 16, polF);
            cp_commit();
        }
        if (c + 1 < NCH) cp_wait<1>();   // chunk c landed
        else             cp_wait<0>();
        __syncthreads();                 // publish chunk c; xsf ready (c==0)

        // ---- compute chunk c: thread (cel, o, ii) does 13 MACs ----
        const int eg = c * CHE + cel;
        const float* xrow = &xsf[eg * IK + ii * KC];

        float acc = 0.0f;
        if (!isbyte) {
            const uint32_t* mrow = mbuf + bsel * CHWRD + cel * WPE + lp * KC;
            #pragma unroll
            for (int k = 0; k < KC; k++)
                if (mrow[k]) acc = fmaf(wreg[k], xrow[k], acc);
        } else {
            const uint8_t* mrow = reinterpret_cast<const uint8_t*>(mbuf) +
                                  bsel * CHB_W + cel * WPE + lp * KC;
            #pragma unroll
            for (int k = 0; k < KC; k++)
                if (mrow[k]) acc = fmaf(wreg[k], xrow[k], acc);
        }

        // reduce over input features (lane bits 0..2)
        acc += __shfl_xor_sync(0xffffffffu, acc, 1);
        acc += __shfl_xor_sync(0xffffffffu, acc, 2);
        acc += __shfl_xor_sync(0xffffffffu, acc, 4);

        if (ii == 0) {
            float z = acc + bsh[o];
            float s = 1.0f / (1.0f + __expf(-z));
            __stcs(&out[(size_t)o * NC + els[eg]], (s - 0.5f) * SCALE);
        }
        __syncthreads();   // buffer bsel free for reuse next iteration
    }
}

extern "C" void kernel_launch(void* const* d_in, const int* in_sizes, int n_in,
                              void* d_out, int out_size) {
    const float*   x   = (const float*)  d_in[0];
    const float*   Wh  = (const float*)  d_in[1];
    const float*   Wv  = (const float*)  d_in[2];
    const float*   bh  = (const float*)  d_in[3];
    const float*   bv  = (const float*)  d_in[4];
    const uint8_t* Mh  = (const uint8_t*)d_in[5];
    const uint8_t* Mv  = (const uint8_t*)d_in[6];
    const int*     Kh  = (const int*)    d_in[7];
    const int*     Kv  = (const int*)    d_in[8];
    const int*     ELh = (const int*)    d_in[9];
    const int*     ELv = (const int*)    d_in[10];
    float* out = (float*)d_out;

    prep_kernel<<<NC / TPB, TPB>>>(x, (const uint32_t*)Mh);

    dim3 grid(L2C / EPB, 2);   // y=0 horizontal branch, y=1 vertical
    edge_kernel<<<grid, TPB>>>(Wh, Wv, bh, bv, Mh, Mv, Kh, Kv, ELh, ELv, out);
}